// round 3
// baseline (speedup 1.0000x reference)
#include <cuda_runtime.h>

// JacobianLayer: J[b] = W3^T diag(1-h2^2) W2^T diag(1-h1^2) W1^T
// B=8192, D=64, H=256.
//
// One CTA per SM (grid=148), 256 threads, grid-stride over batch.
// Smem: W1T [256][64], W3 [256][64], Q scratch [256][64]  (~199 KB)
// Stage1 (fused with h2 forward): thread t owns k=t, accumulates
//   Q[k,j] = g2[k] * sum_l W2[l,k] * g1[l] * W1[j,l]   (64 accs, packed f32x2)
// Stage2: thread t owns a 4x4 tile of J:
//   J[i,j] = sum_k W3[k,i] * Q[k,j]

#define BATCH 8192
#define D 64
#define H 256
#define NTHREADS 256
#define NUM_SMS 148

typedef unsigned long long u64t;

__device__ __forceinline__ u64t pack2(float s) {
    u64t r;
    asm("mov.b64 %0, {%1, %1};" : "=l"(r) : "f"(s));
    return r;
}
__device__ __forceinline__ u64t fma2(u64t a, u64t b, u64t c) {
    u64t d;
    asm("fma.rn.f32x2 %0, %1, %2, %3;" : "=l"(d) : "l"(a), "l"(b), "l"(c));
    return d;
}
__device__ __forceinline__ u64t mul2(u64t a, u64t b) {
    u64t d;
    asm("mul.rn.f32x2 %0, %1, %2;" : "=l"(d) : "l"(a), "l"(b));
    return d;
}
__device__ __forceinline__ float2 unpack2(u64t a) {
    float2 f;
    asm("mov.b64 {%0, %1}, %2;" : "=f"(f.x), "=f"(f.y) : "l"(a));
    return f;
}

__global__ void __launch_bounds__(NTHREADS, 1)
jac_kernel(const float* __restrict__ x,  const float* __restrict__ W1,
           const float* __restrict__ b1, const float* __restrict__ W2,
           const float* __restrict__ b2, const float* __restrict__ W3,
           float* __restrict__ out)
{
    extern __shared__ float sm[];
    float* W1Ts = sm;               // [H][D]: W1T[l][j] = W1[j][l]
    float* W3s  = W1Ts + H * D;     // [H][D]: W3[k][i] (native layout)
    float* Qs   = W3s + H * D;      // [H][D]: Q[k][j] (g2-scaled)
    float* h1s  = Qs + H * D;       // [H]
    float* g1s  = h1s + H;          // [H]
    float* xs   = g1s + H;          // [D]

    const int t = threadIdx.x;

    // ---- one-time weight staging ----
    for (int idx = t; idx < D * H; idx += NTHREADS) {
        const int j = idx / H;          // W1 row (input dim)
        const int l = idx - j * H;      // W1 col (hidden)
        W1Ts[l * D + j] = W1[idx];
    }
    for (int idx = t; idx < H * D; idx += NTHREADS)
        W3s[idx] = W3[idx];
    __syncthreads();

    const float b1t = b1[t];
    const float b2t = b2[t];

    for (int b = blockIdx.x; b < BATCH; b += gridDim.x) {
        // ---- load x[b] ----
        if (t < D) xs[t] = x[(size_t)b * D + t];
        __syncthreads();

        // ---- h1 = tanh(x @ W1 + b1), g1 = 1 - h1^2 ----
        {
            float u0 = 0.f, u1 = 0.f, u2 = 0.f, u3 = 0.f;
            #pragma unroll
            for (int d4 = 0; d4 < D; d4 += 4) {
                u0 = fmaf(xs[d4 + 0], W1[(d4 + 0) * H + t], u0);
                u1 = fmaf(xs[d4 + 1], W1[(d4 + 1) * H + t], u1);
                u2 = fmaf(xs[d4 + 2], W1[(d4 + 2) * H + t], u2);
                u3 = fmaf(xs[d4 + 3], W1[(d4 + 3) * H + t], u3);
            }
            const float h = tanhf((u0 + u1) + (u2 + u3) + b1t);
            h1s[t] = h;
            g1s[t] = 1.0f - h * h;
        }
        __syncthreads();

        // ---- fused: h2 pre-activation + Stage1 ----
        // thread t = column k of W2; acc[j-pair] over 64 j's
        u64t acc[32];
        #pragma unroll
        for (int q = 0; q < 32; q++) acc[q] = 0ull;

        float v0 = b2t, v1 = 0.f;   // h2 pre-activation partials

        #pragma unroll 1
        for (int l0 = 0; l0 < H; l0 += 8) {
            float w2v[8];
            #pragma unroll
            for (int u = 0; u < 8; u++)
                w2v[u] = W2[(l0 + u) * H + t];   // coalesced column reads, MLP=8
            #pragma unroll
            for (int u = 0; u < 8; u++) {
                const int l = l0 + u;
                const float w = w2v[u];
                if (u & 1) v1 = fmaf(h1s[l], w, v1);
                else       v0 = fmaf(h1s[l], w, v0);
                const u64t s2 = pack2(g1s[l] * w);    // fold diag(g1)
                const ulonglong2* wrow = (const ulonglong2*)(W1Ts + l * D);
                #pragma unroll
                for (int q = 0; q < 16; q++) {
                    const ulonglong2 wv = wrow[q];     // broadcast LDS.128
                    acc[2 * q]     = fma2(wv.x, s2, acc[2 * q]);
                    acc[2 * q + 1] = fma2(wv.y, s2, acc[2 * q + 1]);
                }
            }
        }

        // g2 for this k, fold into Q writeback
        const float h2v = tanhf(v0 + v1);
        const u64t g2p = pack2(1.0f - h2v * h2v);
        u64t* qrow = (u64t*)(Qs + t * D);
        #pragma unroll
        for (int q = 0; q < 32; q++) qrow[q] = mul2(acc[q], g2p);
        __syncthreads();

        // ---- Stage2: J[i,j] = sum_k W3[k,i] * Q[k,j]; 4x4 tile per thread ----
        const int j0 = (t & 15) * 4;
        const int i0 = (t >> 4) * 4;
        u64t c00 = 0, c01 = 0, c10 = 0, c11 = 0;
        u64t c20 = 0, c21 = 0, c30 = 0, c31 = 0;
        #pragma unroll 4
        for (int k = 0; k < H; k++) {
            const float4 a4 = *(const float4*)(W3s + k * D + i0);
            const ulonglong2 bv = *(const ulonglong2*)(Qs + k * D + j0);
            u64t a;
            a = pack2(a4.x); c00 = fma2(bv.x, a, c00); c01 = fma2(bv.y, a, c01);
            a = pack2(a4.y); c10 = fma2(bv.x, a, c10); c11 = fma2(bv.y, a, c11);
            a = pack2(a4.z); c20 = fma2(bv.x, a, c20); c21 = fma2(bv.y, a, c21);
            a = pack2(a4.w); c30 = fma2(bv.x, a, c30); c31 = fma2(bv.y, a, c31);
        }

        // ---- writeback 4x4 tile ----
        float* op = out + (size_t)b * (D * D);
        {
            float2 lo, hi;
            lo = unpack2(c00); hi = unpack2(c01);
            *(float4*)(op + (i0 + 0) * D + j0) = make_float4(lo.x, lo.y, hi.x, hi.y);
            lo = unpack2(c10); hi = unpack2(c11);
            *(float4*)(op + (i0 + 1) * D + j0) = make_float4(lo.x, lo.y, hi.x, hi.y);
            lo = unpack2(c20); hi = unpack2(c21);
            *(float4*)(op + (i0 + 2) * D + j0) = make_float4(lo.x, lo.y, hi.x, hi.y);
            lo = unpack2(c30); hi = unpack2(c31);
            *(float4*)(op + (i0 + 3) * D + j0) = make_float4(lo.x, lo.y, hi.x, hi.y);
        }
        __syncthreads();   // protect smem reuse for next batch
    }
}

extern "C" void kernel_launch(void* const* d_in, const int* in_sizes, int n_in,
                              void* d_out, int out_size)
{
    const float* x  = (const float*)d_in[0];
    const float* W1 = (const float*)d_in[1];
    const float* b1 = (const float*)d_in[2];
    const float* W2 = (const float*)d_in[3];
    const float* b2 = (const float*)d_in[4];
    const float* W3 = (const float*)d_in[5];
    // d_in[6] = b3: does not affect the Jacobian
    float* out = (float*)d_out;

    const int smem_bytes = (3 * H * D + 2 * H + D) * (int)sizeof(float); // ~199 KB
    cudaFuncSetAttribute(jac_kernel,
                         cudaFuncAttributeMaxDynamicSharedMemorySize, smem_bytes);
    jac_kernel<<<NUM_SMS, NTHREADS, smem_bytes>>>(x, W1, b1, W2, b2, W3, out);
}

// round 5
// speedup vs baseline: 1.9311x; 1.9311x over previous
#include <cuda_runtime.h>
#include <cstdint>

#define BATCH 8192
#define GRID_C 148
#define P 260          // smem pitch (floats) for 256-wide tiles
#define CP 36          // C1s pitch

__device__ float G1d[2097152]; // [8192][256] = 1 - h1^2
__device__ float G2d[2097152]; // [8192][256] = 1 - h2^2

typedef unsigned long long u64;
__device__ __forceinline__ float rnaf(float f){
    uint32_t o; asm("cvt.rna.tf32.f32 %0, %1;" : "=r"(o) : "f"(f)); return __uint_as_float(o);
}
__device__ __forceinline__ uint32_t rnab(float f){
    uint32_t o; asm("cvt.rna.tf32.f32 %0, %1;" : "=r"(o) : "f"(f)); return o;
}
__device__ __forceinline__ u64 pk2(float s){ u64 r; asm("mov.b64 %0,{%1,%1};" : "=l"(r) : "f"(s)); return r; }
__device__ __forceinline__ u64 fma2(u64 a, u64 b, u64 c){ u64 d; asm("fma.rn.f32x2 %0,%1,%2,%3;" : "=l"(d) : "l"(a), "l"(b), "l"(c)); return d; }

__device__ __forceinline__ void mma8(float* c, const uint32_t* a, const uint32_t* b){
    asm volatile("mma.sync.aligned.m16n8k8.row.col.f32.tf32.tf32.f32 "
        "{%0,%1,%2,%3},{%4,%5,%6,%7},{%8,%9},{%0,%1,%2,%3};"
        : "+f"(c[0]), "+f"(c[1]), "+f"(c[2]), "+f"(c[3])
        : "r"(a[0]), "r"(a[1]), "r"(a[2]), "r"(a[3]), "r"(b[0]), "r"(b[1]));
}
#define CPA(dst, src) asm volatile("cp.async.cg.shared.global [%0],[%1],16;" :: "r"(dst), "l"(src) : "memory")
__device__ __forceinline__ uint32_t su32(const void* p){
    uint32_t a; asm("{.reg .u64 t; cvta.to.shared.u64 t,%1; cvt.u32.u64 %0,t;}" : "=r"(a) : "l"(p)); return a;
}

// ---------------- fwd: exact fp32 g1/g2 for all batches ----------------
__global__ void __launch_bounds__(256, 1) fwd(const float* __restrict__ x, const float* __restrict__ W1,
                                              const float* __restrict__ b1, const float* __restrict__ W2,
                                              const float* __restrict__ b2){
    extern __shared__ float fs[];
    float* xs  = fs;             // [64 j][66]
    float* h1t = fs + 64 * 66;   // [256 l][66]
    const int t = threadIdx.x;
    const int b0 = blockIdx.x * 64;
    for (int r = 0; r < 16; r++){
        int idx = r * 256 + t, b = idx >> 6, j = idx & 63;
        xs[j * 66 + b] = x[(size_t)(b0 + b) * 64 + j];
    }
    __syncthreads();
    u64 acc[32];
    #pragma unroll
    for (int q = 0; q < 32; q++) acc[q] = 0ull;
    for (int j = 0; j < 64; j++){
        u64 wp = pk2(W1[j * 256 + t]);
        const u64* xr = (const u64*)(xs + j * 66);
        #pragma unroll
        for (int q = 0; q < 32; q++) acc[q] = fma2(xr[q], wp, acc[q]);
    }
    float bb = b1[t];
    #pragma unroll
    for (int q = 0; q < 32; q++){
        float2 f; asm("mov.b64 {%0,%1},%2;" : "=f"(f.x), "=f"(f.y) : "l"(acc[q]));
        float ha = tanhf(f.x + bb), hb = tanhf(f.y + bb);
        h1t[t * 66 + 2*q] = ha; h1t[t * 66 + 2*q + 1] = hb;
        G1d[(size_t)(b0 + 2*q) * 256 + t]     = 1.f - ha * ha;
        G1d[(size_t)(b0 + 2*q + 1) * 256 + t] = 1.f - hb * hb;
    }
    __syncthreads();
    #pragma unroll
    for (int q = 0; q < 32; q++) acc[q] = 0ull;
    for (int l = 0; l < 256; l++){
        u64 wp = pk2(W2[l * 256 + t]);
        const u64* hr = (const u64*)(h1t + l * 66);
        #pragma unroll
        for (int q = 0; q < 32; q++) acc[q] = fma2(hr[q], wp, acc[q]);
    }
    bb = b2[t];
    #pragma unroll
    for (int q = 0; q < 32; q++){
        float2 f; asm("mov.b64 {%0,%1},%2;" : "=f"(f.x), "=f"(f.y) : "l"(acc[q]));
        float ha = tanhf(f.x + bb), hb = tanhf(f.y + bb);
        G2d[(size_t)(b0 + 2*q) * 256 + t]     = 1.f - ha * ha;
        G2d[(size_t)(b0 + 2*q + 1) * 256 + t] = 1.f - hb * hb;
    }
}

// ---------------- jmain: two chained tf32 mma.sync GEMMs per batch ----------------
// smem floats: W1s [64][P], A1s [64][P], W2c [2][32][P], C1s [64][CP], g1s[256], g2s[256]
#define SM_FLOATS (64*P + 64*P + 2*32*P + 64*CP + 512)

__global__ void __launch_bounds__(256, 1) jmain(const float* __restrict__ W1, const float* __restrict__ W2,
                                                const float* __restrict__ W3, float* __restrict__ out){
    extern __shared__ float s[];
    float* W1s = s;
    float* A1s = W1s + 64 * P;
    float* W2c = A1s + 64 * P;
    float* C1s = W2c + 2 * 32 * P;
    float* g1s = C1s + 64 * CP;
    float* g2s = g1s + 256;

    const int t = threadIdx.x;
    const int lane = t & 31, wid = t >> 5;
    const int g = lane >> 2, tg = lane & 3;
    const int mw = wid & 1, nw = wid >> 1;   // 2 x 4 warp grid

    // W1 tf32 image, resident
    for (int idx = t; idx < 16384; idx += 256){
        int j = idx >> 8, l = idx & 255;
        W1s[j * P + l] = rnaf(W1[idx]);
    }
    __syncthreads();

    const uint32_t w2cb = su32(W2c);

    for (int b = blockIdx.x; b < BATCH; b += GRID_C){
        g1s[t] = G1d[(size_t)b * 256 + t];
        g2s[t] = G2d[(size_t)b * 256 + t];
        __syncthreads();
        // A1[m][k] = rna(W3[k][m] * g2[k])
        for (int idx = t; idx < 16384; idx += 256){
            int k = idx >> 6, m = idx & 63;
            A1s[m * P + k] = rnaf(W3[idx] * g2s[k]);
        }
        // prefetch W2 chunk 0
        {
            #pragma unroll
            for (int i = 0; i < 8; i++){
                int u = t + i * 256, row = u >> 6, col = (u & 63) * 4;
                CPA(w2cb + (uint32_t)(row * P + col) * 4, W2 + row * 256 + col);
            }
            asm volatile("cp.async.commit_group;" ::: "memory");
        }

        float J[2][2][4];
        #pragma unroll
        for (int a = 0; a < 2; a++)
            #pragma unroll
            for (int n = 0; n < 2; n++)
                #pragma unroll
                for (int q = 0; q < 4; q++) J[a][n][q] = 0.f;

        #pragma unroll 1
        for (int c = 0; c < 8; c++){
            const int buf = c & 1;
            if (c < 7){
                const int nb = (c + 1) & 1;
                const float* src0 = W2 + (c + 1) * 32 * 256;
                #pragma unroll
                for (int i = 0; i < 8; i++){
                    int u = t + i * 256, row = u >> 6, col = (u & 63) * 4;
                    CPA(w2cb + (uint32_t)(nb * 32 * P + row * P + col) * 4, src0 + row * 256 + col);
                }
                asm volatile("cp.async.commit_group;\ncp.async.wait_group 1;" ::: "memory");
            } else {
                asm volatile("cp.async.wait_group 0;" ::: "memory");
            }
            __syncthreads();

            // ---- GEMM1 chunk: C1r[mt][4] += A1[m, k] * W2[l, k] ----
            float C1r[2][4] = {{0,0,0,0},{0,0,0,0}};
            const float* ap = A1s + (mw * 32 + g) * P + tg;
            const float* bp = W2c + buf * 32 * P + (nw * 8 + g) * P + tg;
            #pragma unroll 4
            for (int k = 0; k < 32; k++){
                uint32_t a0[4], a1[4], bb[2];
                const float* a = ap + k * 8;
                a0[0] = __float_as_uint(a[0]);        a0[1] = __float_as_uint(a[8*P]);
                a0[2] = __float_as_uint(a[4]);        a0[3] = __float_as_uint(a[8*P+4]);
                a1[0] = __float_as_uint(a[16*P]);     a1[1] = __float_as_uint(a[24*P]);
                a1[2] = __float_as_uint(a[16*P+4]);   a1[3] = __float_as_uint(a[24*P+4]);
                bb[0] = rnab(bp[k*8]);                bb[1] = rnab(bp[k*8+4]);
                mma8(C1r[0], a0, bb);
                mma8(C1r[1], a1, bb);
            }
            // ---- scale by g1, park as A2 (tf32) ----
            {
                const int nl0 = nw * 8 + 2 * tg;
                const float gl0 = g1s[c * 32 + nl0], gl1 = g1s[c * 32 + nl0 + 1];
                const int r0 = mw * 32 + g;
                C1s[ r0      * CP + nl0    ] = rnaf(C1r[0][0] * gl0);
                C1s[ r0      * CP + nl0 + 1] = rnaf(C1r[0][1] * gl1);
                C1s[(r0 + 8) * CP + nl0    ] = rnaf(C1r[0][2] * gl0);
                C1s[(r0 + 8) * CP + nl0 + 1] = rnaf(C1r[0][3] * gl1);
                C1s[(r0 +16) * CP + nl0    ] = rnaf(C1r[1][0] * gl0);
                C1s[(r0 +16) * CP + nl0 + 1] = rnaf(C1r[1][1] * gl1);
                C1s[(r0 +24) * CP + nl0    ] = rnaf(C1r[1][2] * gl0);
                C1s[(r0 +24) * CP + nl0 + 1] = rnaf(C1r[1][3] * gl1);
            }
            __syncthreads();

            // ---- GEMM2 partial: J += A2[m, l] * W1[j, l] over this chunk ----
            {
                const float* a2p = C1s + (mw * 32 + g) * CP + tg;
                const float* b0p = W1s + (nw * 16 + g) * P + c * 32 + tg;
                const float* b1p = b0p + 8 * P;
                #pragma unroll
                for (int k = 0; k < 4; k++){
                    uint32_t a0[4], a1[4], bb0[2], bb1[2];
                    const float* a = a2p + k * 8;
                    a0[0] = __float_as_uint(a[0]);        a0[1] = __float_as_uint(a[8*CP]);
                    a0[2] = __float_as_uint(a[4]);        a0[3] = __float_as_uint(a[8*CP+4]);
                    a1[0] = __float_as_uint(a[16*CP]);    a1[1] = __float_as_uint(a[24*CP]);
                    a1[2] = __float_as_uint(a[16*CP+4]);  a1[3] = __float_as_uint(a[24*CP+4]);
                    bb0[0] = __float_as_uint(b0p[k*8]);   bb0[1] = __float_as_uint(b0p[k*8+4]);
                    bb1[0] = __float_as_uint(b1p[k*8]);   bb1[1] = __float_as_uint(b1p[k*8+4]);
                    mma8(J[0][0], a0, bb0);
                    mma8(J[0][1], a0, bb1);
                    mma8(J[1][0], a1, bb0);
                    mma8(J[1][1], a1, bb1);
                }
            }
        }

        // ---- epilogue: J[m][j] -> out[b][m][j] ----
        {
            float* ob = out + (size_t)b * 4096;
            const int col = nw * 16 + 2 * tg;
            #pragma unroll
            for (int mt = 0; mt < 2; mt++){
                const int r0 = mw * 32 + g + mt * 16;
                #pragma unroll
                for (int nt = 0; nt < 2; nt++){
                    const int cc = col + nt * 8;
                    *(float2*)(ob + (size_t)r0 * 64 + cc)       = make_float2(J[mt][nt][0], J[mt][nt][1]);
                    *(float2*)(ob + (size_t)(r0 + 8) * 64 + cc) = make_float2(J[mt][nt][2], J[mt][nt][3]);
                }
            }
        }
        __syncthreads();
    }
}

extern "C" void kernel_launch(void* const* d_in, const int* in_sizes, int n_in,
                              void* d_out, int out_size)
{
    const float* x  = (const float*)d_in[0];
    const float* W1 = (const float*)d_in[1];
    const float* b1 = (const float*)d_in[2];
    const float* W2 = (const float*)d_in[3];
    const float* b2 = (const float*)d_in[4];
    const float* W3 = (const float*)d_in[5];
    float* out = (float*)d_out;

    cudaFuncSetAttribute(fwd,   cudaFuncAttributeMaxDynamicSharedMemorySize, (64*66 + 256*66) * 4);
    cudaFuncSetAttribute(jmain, cudaFuncAttributeMaxDynamicSharedMemorySize, SM_FLOATS * 4);

    fwd<<<128, 256, (64*66 + 256*66) * 4>>>(x, W1, b1, W2, b2);
    jmain<<<GRID_C, 256, SM_FLOATS * 4>>>(W1, W2, W3, out);
}

// round 6
// speedup vs baseline: 1.9316x; 1.0003x over previous
#include <cuda_runtime.h>
#include <cstdint>

#define BATCH 8192
#define GRID_C 148
#define P 260          // smem pitch (floats) for 256-wide tiles
#define CP 36          // C1s pitch

__device__ float G1d[2097152]; // [8192][256] = 1 - h1^2
__device__ float G2d[2097152]; // [8192][256] = 1 - h2^2

typedef unsigned long long u64;
__device__ __forceinline__ float rnaf(float f){
    uint32_t o; asm("cvt.rna.tf32.f32 %0, %1;" : "=r"(o) : "f"(f)); return __uint_as_float(o);
}
__device__ __forceinline__ uint32_t rnab(float f){
    uint32_t o; asm("cvt.rna.tf32.f32 %0, %1;" : "=r"(o) : "f"(f)); return o;
}
__device__ __forceinline__ u64 pk2(float s){ u64 r; asm("mov.b64 %0,{%1,%1};" : "=l"(r) : "f"(s)); return r; }
__device__ __forceinline__ u64 fma2(u64 a, u64 b, u64 c){ u64 d; asm("fma.rn.f32x2 %0,%1,%2,%3;" : "=l"(d) : "l"(a), "l"(b), "l"(c)); return d; }

__device__ __forceinline__ void mma8(float* c, const uint32_t* a, const uint32_t* b){
    asm volatile("mma.sync.aligned.m16n8k8.row.col.f32.tf32.tf32.f32 "
        "{%0,%1,%2,%3},{%4,%5,%6,%7},{%8,%9},{%0,%1,%2,%3};"
        : "+f"(c[0]), "+f"(c[1]), "+f"(c[2]), "+f"(c[3])
        : "r"(a[0]), "r"(a[1]), "r"(a[2]), "r"(a[3]), "r"(b[0]), "r"(b[1]));
}
#define CPA(dst, src) asm volatile("cp.async.cg.shared.global [%0],[%1],16;" :: "r"(dst), "l"(src) : "memory")
__device__ __forceinline__ uint32_t su32(const void* p){
    uint32_t a; asm("{.reg .u64 t; cvta.to.shared.u64 t,%1; cvt.u32.u64 %0,t;}" : "=r"(a) : "l"(p)); return a;
}

// ---------------- fwd: exact fp32 g1/g2 for all batches ----------------
__global__ void __launch_bounds__(256, 1) fwd(const float* __restrict__ x, const float* __restrict__ W1,
                                              const float* __restrict__ b1, const float* __restrict__ W2,
                                              const float* __restrict__ b2){
    extern __shared__ float fs[];
    float* xs  = fs;             // [64 j][66]
    float* h1t = fs + 64 * 66;   // [256 l][66]
    const int t = threadIdx.x;
    const int b0 = blockIdx.x * 64;
    for (int r = 0; r < 16; r++){
        int idx = r * 256 + t, b = idx >> 6, j = idx & 63;
        xs[j * 66 + b] = x[(size_t)(b0 + b) * 64 + j];
    }
    __syncthreads();
    u64 acc[32];
    #pragma unroll
    for (int q = 0; q < 32; q++) acc[q] = 0ull;
    for (int j = 0; j < 64; j++){
        u64 wp = pk2(W1[j * 256 + t]);
        const u64* xr = (const u64*)(xs + j * 66);
        #pragma unroll
        for (int q = 0; q < 32; q++) acc[q] = fma2(xr[q], wp, acc[q]);
    }
    float bb = b1[t];
    #pragma unroll
    for (int q = 0; q < 32; q++){
        float2 f; asm("mov.b64 {%0,%1},%2;" : "=f"(f.x), "=f"(f.y) : "l"(acc[q]));
        float ha = tanhf(f.x + bb), hb = tanhf(f.y + bb);
        h1t[t * 66 + 2*q] = ha; h1t[t * 66 + 2*q + 1] = hb;
        G1d[(size_t)(b0 + 2*q) * 256 + t]     = 1.f - ha * ha;
        G1d[(size_t)(b0 + 2*q + 1) * 256 + t] = 1.f - hb * hb;
    }
    __syncthreads();
    #pragma unroll
    for (int q = 0; q < 32; q++) acc[q] = 0ull;
    for (int l = 0; l < 256; l++){
        u64 wp = pk2(W2[l * 256 + t]);
        const u64* hr = (const u64*)(h1t + l * 66);
        #pragma unroll
        for (int q = 0; q < 32; q++) acc[q] = fma2(hr[q], wp, acc[q]);
    }
    bb = b2[t];
    #pragma unroll
    for (int q = 0; q < 32; q++){
        float2 f; asm("mov.b64 {%0,%1},%2;" : "=f"(f.x), "=f"(f.y) : "l"(acc[q]));
        float ha = tanhf(f.x + bb), hb = tanhf(f.y + bb);
        G2d[(size_t)(b0 + 2*q) * 256 + t]     = 1.f - ha * ha;
        G2d[(size_t)(b0 + 2*q + 1) * 256 + t] = 1.f - hb * hb;
    }
}

// ---------------- jmain: two chained tf32 mma.sync GEMMs per batch ----------------
// smem floats: W1s [64][P], A1s [64][P], W2c [2][32][P], C1s [64][CP], g1s[256], g2s[256]
#define SM_FLOATS (64*P + 64*P + 2*32*P + 64*CP + 512)

__global__ void __launch_bounds__(256, 1) jmain(const float* __restrict__ W1, const float* __restrict__ W2,
                                                const float* __restrict__ W3, float* __restrict__ out){
    extern __shared__ float s[];
    float* W1s = s;
    float* A1s = W1s + 64 * P;
    float* W2c = A1s + 64 * P;
    float* C1s = W2c + 2 * 32 * P;
    float* g1s = C1s + 64 * CP;
    float* g2s = g1s + 256;

    const int t = threadIdx.x;
    const int lane = t & 31, wid = t >> 5;
    const int g = lane >> 2, tg = lane & 3;
    const int mw = wid & 1, nw = wid >> 1;   // 2 x 4 warp grid

    // W1 tf32 image, resident
    for (int idx = t; idx < 16384; idx += 256){
        int j = idx >> 8, l = idx & 255;
        W1s[j * P + l] = rnaf(W1[idx]);
    }
    __syncthreads();

    const uint32_t w2cb = su32(W2c);

    for (int b = blockIdx.x; b < BATCH; b += GRID_C){
        g1s[t] = G1d[(size_t)b * 256 + t];
        g2s[t] = G2d[(size_t)b * 256 + t];
        __syncthreads();
        // A1[m][k] = rna(W3[k][m] * g2[k])
        for (int idx = t; idx < 16384; idx += 256){
            int k = idx >> 6, m = idx & 63;
            A1s[m * P + k] = rnaf(W3[idx] * g2s[k]);
        }
        // prefetch W2 chunk 0
        {
            #pragma unroll
            for (int i = 0; i < 8; i++){
                int u = t + i * 256, row = u >> 6, col = (u & 63) * 4;
                CPA(w2cb + (uint32_t)(row * P + col) * 4, W2 + row * 256 + col);
            }
            asm volatile("cp.async.commit_group;" ::: "memory");
        }

        float J[2][2][4];
        #pragma unroll
        for (int a = 0; a < 2; a++)
            #pragma unroll
            for (int n = 0; n < 2; n++)
                #pragma unroll
                for (int q = 0; q < 4; q++) J[a][n][q] = 0.f;

        #pragma unroll 1
        for (int c = 0; c < 8; c++){
            const int buf = c & 1;
            if (c < 7){
                const int nb = (c + 1) & 1;
                const float* src0 = W2 + (c + 1) * 32 * 256;
                #pragma unroll
                for (int i = 0; i < 8; i++){
                    int u = t + i * 256, row = u >> 6, col = (u & 63) * 4;
                    CPA(w2cb + (uint32_t)(nb * 32 * P + row * P + col) * 4, src0 + row * 256 + col);
                }
                asm volatile("cp.async.commit_group;\ncp.async.wait_group 1;" ::: "memory");
            } else {
                asm volatile("cp.async.wait_group 0;" ::: "memory");
            }
            __syncthreads();

            // ---- GEMM1 chunk: C1r[mt][4] += A1[m, k] * W2[l, k] ----
            float C1r[2][4] = {{0,0,0,0},{0,0,0,0}};
            const float* ap = A1s + (mw * 32 + g) * P + tg;
            const float* bp = W2c + buf * 32 * P + (nw * 8 + g) * P + tg;
            #pragma unroll 4
            for (int k = 0; k < 32; k++){
                uint32_t a0[4], a1[4], bb[2];
                const float* a = ap + k * 8;
                a0[0] = __float_as_uint(a[0]);        a0[1] = __float_as_uint(a[8*P]);
                a0[2] = __float_as_uint(a[4]);        a0[3] = __float_as_uint(a[8*P+4]);
                a1[0] = __float_as_uint(a[16*P]);     a1[1] = __float_as_uint(a[24*P]);
                a1[2] = __float_as_uint(a[16*P+4]);   a1[3] = __float_as_uint(a[24*P+4]);
                bb[0] = rnab(bp[k*8]);                bb[1] = rnab(bp[k*8+4]);
                mma8(C1r[0], a0, bb);
                mma8(C1r[1], a1, bb);
            }
            // ---- scale by g1, park as A2 (tf32) ----
            {
                const int nl0 = nw * 8 + 2 * tg;
                const float gl0 = g1s[c * 32 + nl0], gl1 = g1s[c * 32 + nl0 + 1];
                const int r0 = mw * 32 + g;
                C1s[ r0      * CP + nl0    ] = rnaf(C1r[0][0] * gl0);
                C1s[ r0      * CP + nl0 + 1] = rnaf(C1r[0][1] * gl1);
                C1s[(r0 + 8) * CP + nl0    ] = rnaf(C1r[0][2] * gl0);
                C1s[(r0 + 8) * CP + nl0 + 1] = rnaf(C1r[0][3] * gl1);
                C1s[(r0 +16) * CP + nl0    ] = rnaf(C1r[1][0] * gl0);
                C1s[(r0 +16) * CP + nl0 + 1] = rnaf(C1r[1][1] * gl1);
                C1s[(r0 +24) * CP + nl0    ] = rnaf(C1r[1][2] * gl0);
                C1s[(r0 +24) * CP + nl0 + 1] = rnaf(C1r[1][3] * gl1);
            }
            __syncthreads();

            // ---- GEMM2 partial: J += A2[m, l] * W1[j, l] over this chunk ----
            {
                const float* a2p = C1s + (mw * 32 + g) * CP + tg;
                const float* b0p = W1s + (nw * 16 + g) * P + c * 32 + tg;
                const float* b1p = b0p + 8 * P;
                #pragma unroll
                for (int k = 0; k < 4; k++){
                    uint32_t a0[4], a1[4], bb0[2], bb1[2];
                    const float* a = a2p + k * 8;
                    a0[0] = __float_as_uint(a[0]);        a0[1] = __float_as_uint(a[8*CP]);
                    a0[2] = __float_as_uint(a[4]);        a0[3] = __float_as_uint(a[8*CP+4]);
                    a1[0] = __float_as_uint(a[16*CP]);    a1[1] = __float_as_uint(a[24*CP]);
                    a1[2] = __float_as_uint(a[16*CP+4]);  a1[3] = __float_as_uint(a[24*CP+4]);
                    bb0[0] = __float_as_uint(b0p[k*8]);   bb0[1] = __float_as_uint(b0p[k*8+4]);
                    bb1[0] = __float_as_uint(b1p[k*8]);   bb1[1] = __float_as_uint(b1p[k*8+4]);
                    mma8(J[0][0], a0, bb0);
                    mma8(J[0][1], a0, bb1);
                    mma8(J[1][0], a1, bb0);
                    mma8(J[1][1], a1, bb1);
                }
            }
        }

        // ---- epilogue: J[m][j] -> out[b][m][j] ----
        {
            float* ob = out + (size_t)b * 4096;
            const int col = nw * 16 + 2 * tg;
            #pragma unroll
            for (int mt = 0; mt < 2; mt++){
                const int r0 = mw * 32 + g + mt * 16;
                #pragma unroll
                for (int nt = 0; nt < 2; nt++){
                    const int cc = col + nt * 8;
                    *(float2*)(ob + (size_t)r0 * 64 + cc)       = make_float2(J[mt][nt][0], J[mt][nt][1]);
                    *(float2*)(ob + (size_t)(r0 + 8) * 64 + cc) = make_float2(J[mt][nt][2], J[mt][nt][3]);
                }
            }
        }
        __syncthreads();
    }
}

extern "C" void kernel_launch(void* const* d_in, const int* in_sizes, int n_in,
                              void* d_out, int out_size)
{
    const float* x  = (const float*)d_in[0];
    const float* W1 = (const float*)d_in[1];
    const float* b1 = (const float*)d_in[2];
    const float* W2 = (const float*)d_in[3];
    const float* b2 = (const float*)d_in[4];
    const float* W3 = (const float*)d_in[5];
    float* out = (float*)d_out;

    cudaFuncSetAttribute(fwd,   cudaFuncAttributeMaxDynamicSharedMemorySize, (64*66 + 256*66) * 4);
    cudaFuncSetAttribute(jmain, cudaFuncAttributeMaxDynamicSharedMemorySize, SM_FLOATS * 4);

    fwd<<<128, 256, (64*66 + 256*66) * 4>>>(x, W1, b1, W2, b2);
    jmain<<<GRID_C, 256, SM_FLOATS * 4>>>(W1, W2, W3, out);
}

// round 7
// speedup vs baseline: 2.5786x; 1.3349x over previous
#include <cuda_runtime.h>
#include <cstdint>

#define GRID_C 148

__device__ float G1d[2097152]; // [8192][256] = 1 - h1^2
__device__ float G2d[2097152]; // [8192][256] = 1 - h2^2
__device__ float W2P[65536];   // fragment-permuted tf32 W2: [c][lt][ks][lane][2]
__device__ float W1P[16384];   // fragment-permuted tf32 W1: [jt][ksg][lane][2]

typedef unsigned long long u64;
__device__ __forceinline__ float rnaf(float f){
    uint32_t o; asm("cvt.rna.tf32.f32 %0, %1;" : "=r"(o) : "f"(f)); return __uint_as_float(o);
}
__device__ __forceinline__ u64 pk2(float s){ u64 r; asm("mov.b64 %0,{%1,%1};" : "=l"(r) : "f"(s)); return r; }
__device__ __forceinline__ u64 fma2(u64 a, u64 b, u64 c){ u64 d; asm("fma.rn.f32x2 %0,%1,%2,%3;" : "=l"(d) : "l"(a), "l"(b), "l"(c)); return d; }
__device__ __forceinline__ void mma8(float* c, const uint32_t* a, const uint32_t* b){
    asm volatile("mma.sync.aligned.m16n8k8.row.col.f32.tf32.tf32.f32 "
        "{%0,%1,%2,%3},{%4,%5,%6,%7},{%8,%9},{%0,%1,%2,%3};"
        : "+f"(c[0]), "+f"(c[1]), "+f"(c[2]), "+f"(c[3])
        : "r"(a[0]), "r"(a[1]), "r"(a[2]), "r"(a[3]), "r"(b[0]), "r"(b[1]));
}
#define CPA(dst, src) asm volatile("cp.async.cg.shared.global [%0],[%1],16;" :: "r"(dst), "l"(src) : "memory")
__device__ __forceinline__ uint32_t su32(const void* p){
    uint32_t a; asm("{.reg .u64 t; cvta.to.shared.u64 t,%1; cvt.u32.u64 %0,t;}" : "=r"(a) : "l"(p)); return a;
}
#define WGBAR(id) asm volatile("bar.sync %0, 256;" :: "r"(id) : "memory")

// ---------------- prep: fragment-permuted tf32 weight images ----------------
__global__ void prep(const float* __restrict__ W1, const float* __restrict__ W2){
    int i = blockIdx.x * blockDim.x + threadIdx.x, stride = gridDim.x * blockDim.x;
    for (int idx = i; idx < 65536; idx += stride){
        int w = idx & 1, lane = (idx >> 1) & 31, ks = (idx >> 6) & 31, lt = (idx >> 11) & 3, c = idx >> 13;
        int l = c * 32 + lt * 8 + (lane >> 2), k = ks * 8 + (lane & 3) + 4 * w;
        W2P[idx] = rnaf(W2[l * 256 + k]);
    }
    for (int idx = i; idx < 16384; idx += stride){
        int w = idx & 1, lane = (idx >> 1) & 31, ksg = (idx >> 6) & 31, jt = idx >> 11;
        int j = jt * 8 + (lane >> 2), l = ksg * 8 + (lane & 3) + 4 * w;
        W1P[idx] = rnaf(W1[j * 256 + l]);
    }
}

// ---------------- fwd: exact fp32 g1/g2 for all batches ----------------
__global__ void __launch_bounds__(256, 1) fwd(const float* __restrict__ x, const float* __restrict__ W1,
                                              const float* __restrict__ b1, const float* __restrict__ W2,
                                              const float* __restrict__ b2){
    extern __shared__ float fs[];
    float* xs  = fs;             // [64 j][66]
    float* h1t = fs + 64 * 66;   // [256 l][66]
    const int t = threadIdx.x;
    const int b0 = blockIdx.x * 64;
    for (int r = 0; r < 16; r++){
        int idx = r * 256 + t, b = idx >> 6, j = idx & 63;
        xs[j * 66 + b] = x[(size_t)(b0 + b) * 64 + j];
    }
    __syncthreads();
    u64 acc[32];
    #pragma unroll
    for (int q = 0; q < 32; q++) acc[q] = 0ull;
    for (int j = 0; j < 64; j++){
        u64 wp = pk2(W1[j * 256 + t]);
        const u64* xr = (const u64*)(xs + j * 66);
        #pragma unroll
        for (int q = 0; q < 32; q++) acc[q] = fma2(xr[q], wp, acc[q]);
    }
    float bb = b1[t];
    #pragma unroll
    for (int q = 0; q < 32; q++){
        float2 f; asm("mov.b64 {%0,%1},%2;" : "=f"(f.x), "=f"(f.y) : "l"(acc[q]));
        float ha = tanhf(f.x + bb), hb = tanhf(f.y + bb);
        h1t[t * 66 + 2*q] = ha; h1t[t * 66 + 2*q + 1] = hb;
        G1d[(size_t)(b0 + 2*q) * 256 + t]     = 1.f - ha * ha;
        G1d[(size_t)(b0 + 2*q + 1) * 256 + t] = 1.f - hb * hb;
    }
    __syncthreads();
    #pragma unroll
    for (int q = 0; q < 32; q++) acc[q] = 0ull;
    for (int l = 0; l < 256; l++){
        u64 wp = pk2(W2[l * 256 + t]);
        const u64* hr = (const u64*)(h1t + l * 66);
        #pragma unroll
        for (int q = 0; q < 32; q++) acc[q] = fma2(hr[q], wp, acc[q]);
    }
    bb = b2[t];
    #pragma unroll
    for (int q = 0; q < 32; q++){
        float2 f; asm("mov.b64 {%0,%1},%2;" : "=f"(f.x), "=f"(f.y) : "l"(acc[q]));
        float ha = tanhf(f.x + bb), hb = tanhf(f.y + bb);
        G2d[(size_t)(b0 + 2*q) * 256 + t]     = 1.f - ha * ha;
        G2d[(size_t)(b0 + 2*q + 1) * 256 + t] = 1.f - hb * hb;
    }
}

// ---------------- jmain: 512 threads, 2 batches/CTA (one per warpgroup) ----------------
// smem floats: A1P[2][16384]  W2c[2][8192]  C1P[2][2048]  g1s[2][256]  g2s[2][256]
#define SMF (32768 + 16384 + 4096 + 1024)

__global__ void __launch_bounds__(512, 1) jmain(const float* __restrict__ W3, float* __restrict__ out){
    extern __shared__ float s[];
    float* A1P = s;                  // 2 x 16384
    float* W2c = s + 32768;          // 2 x 8192 (chunk double buffer)
    float* C1P = W2c + 16384;        // 2 x 2048
    float* g1s = C1P + 4096;         // 2 x 256
    float* g2s = g1s + 512;          // 2 x 256

    const int t = threadIdx.x, lane = t & 31, wid = t >> 5;
    const int wg = wid >> 3, w8 = wid & 7, mw = w8 & 1, nw = w8 >> 1;
    const int t2 = t & 255;
    const int g = lane >> 2, tg = lane & 3;

    float* A1w = A1P + wg * 16384;
    float* C1w = C1P + wg * 2048;
    float* g1w = g1s + wg * 256;
    float* g2w = g2s + wg * 256;
    const uint32_t w2cb = su32(W2c);
    const float4* A1w4 = (const float4*)A1w;
    const float4* C1w4 = (const float4*)C1w;
    const float2* W1P2 = (const float2*)W1P;

    for (int p = blockIdx.x; p < 4096; p += GRID_C){
        const int b = 2 * p + wg;
        g1w[t2] = G1d[(size_t)b * 256 + t2];
        g2w[t2] = G2d[(size_t)b * 256 + t2];
        WGBAR(1 + wg);

        // build A1 in fragment-permuted layout: A1P[mt][ks][lane]{4}
        #pragma unroll
        for (int i = 0; i < 16; i++){
            int f = i * 256 + t2;
            int ln = f & 31, ks = (f >> 5) & 31, mt = f >> 10;
            int gg = ln >> 2, tt = ln & 3, m0 = mt * 16 + gg, k0 = ks * 8 + tt;
            float ga = g2w[k0], gb = g2w[k0 + 4];
            float4 v;
            v.x = rnaf(W3[k0 * 64 + m0] * ga);
            v.y = rnaf(W3[k0 * 64 + m0 + 8] * ga);
            v.z = rnaf(W3[(k0 + 4) * 64 + m0] * gb);
            v.w = rnaf(W3[(k0 + 4) * 64 + m0 + 8] * gb);
            ((float4*)A1w)[f] = v;
        }
        // prefetch W2 chunk 0
        #pragma unroll
        for (int i = 0; i < 4; i++){
            int u = t + i * 512;
            CPA(w2cb + (uint32_t)u * 16, (const char*)W2P + u * 16);
        }
        asm volatile("cp.async.commit_group;" ::: "memory");

        float J[2][2][4];
        #pragma unroll
        for (int a = 0; a < 2; a++)
            #pragma unroll
            for (int n = 0; n < 2; n++)
                #pragma unroll
                for (int q = 0; q < 4; q++) J[a][n][q] = 0.f;

        #pragma unroll 1
        for (int c = 0; c < 8; c++){
            const int buf = c & 1;
            if (c < 7){
                const int nb = (c + 1) & 1;
                #pragma unroll
                for (int i = 0; i < 4; i++){
                    int u = t + i * 512;
                    CPA(w2cb + (uint32_t)(nb * 32768 + u * 16), (const char*)W2P + (c + 1) * 32768 + u * 16);
                }
                asm volatile("cp.async.commit_group;\ncp.async.wait_group 1;" ::: "memory");
            } else {
                asm volatile("cp.async.wait_group 0;" ::: "memory");
            }
            __syncthreads();

            // ---- GEMM1 chunk: C1r += A1 x W2chunk (vector fragment loads) ----
            float C1r[2][4] = {{0,0,0,0},{0,0,0,0}};
            const float4* a0p = A1w4 + (2 * mw) * 1024 + lane;
            const float2* bp  = (const float2*)(W2c + buf * 8192) + nw * 1024 + lane;
            #pragma unroll 8
            for (int ks = 0; ks < 32; ks++){
                float4 A0 = a0p[ks * 32];
                float4 A1 = a0p[1024 + ks * 32];
                float2 B  = bp[ks * 32];
                mma8(C1r[0], (const uint32_t*)&A0, (const uint32_t*)&B);
                mma8(C1r[1], (const uint32_t*)&A1, (const uint32_t*)&B);
            }

            // ---- scale by g1, park into fragment-permuted C1P ----
            #pragma unroll
            for (int h = 0; h < 2; h++){
                const int mt = 2 * mw + h;
                #pragma unroll
                for (int q = 0; q < 4; q++){
                    const int rr = g + 8 * (q >> 1);
                    const int cc = 2 * tg + (q & 1);
                    const float gl = g1w[c * 32 + nw * 8 + cc];
                    const int fi = ((mt * 4 + nw) * 32 + g * 4 + (cc & 3)) * 4 + (rr >> 3) + 2 * (cc >> 2);
                    C1w[fi] = rnaf(C1r[h][q] * gl);
                }
            }
            WGBAR(1 + wg);

            // ---- GEMM2 partial: J += A2 x W1chunk ----
            {
                const float4* a2p = C1w4 + (2 * mw) * 128 + lane;
                const float2* b0p = W1P2 + ((2 * nw) * 32 + c * 4) * 32 + lane;
                #pragma unroll
                for (int ks2 = 0; ks2 < 4; ks2++){
                    float4 A0 = a2p[ks2 * 32];
                    float4 A1 = a2p[128 + ks2 * 32];
                    float2 B0 = b0p[ks2 * 32];
                    float2 B1 = b0p[1024 + ks2 * 32];
                    mma8(J[0][0], (const uint32_t*)&A0, (const uint32_t*)&B0);
                    mma8(J[0][1], (const uint32_t*)&A0, (const uint32_t*)&B1);
                    mma8(J[1][0], (const uint32_t*)&A1, (const uint32_t*)&B0);
                    mma8(J[1][1], (const uint32_t*)&A1, (const uint32_t*)&B1);
                }
            }
        }

        // ---- epilogue ----
        {
            float* ob = out + (size_t)b * 4096;
            const int col = nw * 16 + 2 * tg;
            #pragma unroll
            for (int mt = 0; mt < 2; mt++){
                const int r0 = mw * 32 + g + mt * 16;
                #pragma unroll
                for (int nt = 0; nt < 2; nt++){
                    const int cc = col + nt * 8;
                    *(float2*)(ob + (size_t)r0 * 64 + cc)       = make_float2(J[mt][nt][0], J[mt][nt][1]);
                    *(float2*)(ob + (size_t)(r0 + 8) * 64 + cc) = make_float2(J[mt][nt][2], J[mt][nt][3]);
                }
            }
        }
        __syncthreads();
    }
}

extern "C" void kernel_launch(void* const* d_in, const int* in_sizes, int n_in,
                              void* d_out, int out_size)
{
    const float* x  = (const float*)d_in[0];
    const float* W1 = (const float*)d_in[1];
    const float* b1 = (const float*)d_in[2];
    const float* W2 = (const float*)d_in[3];
    const float* b2 = (const float*)d_in[4];
    const float* W3 = (const float*)d_in[5];
    float* out = (float*)d_out;

    cudaFuncSetAttribute(fwd,   cudaFuncAttributeMaxDynamicSharedMemorySize, (64*66 + 256*66) * 4);
    cudaFuncSetAttribute(jmain, cudaFuncAttributeMaxDynamicSharedMemorySize, SMF * 4);

    prep<<<64, 256>>>(W1, W2);
    fwd<<<128, 256, (64*66 + 256*66) * 4>>>(x, W1, b1, W2, b2);
    jmain<<<GRID_C, 512, SMF * 4>>>(W3, out);
}

// round 9
// speedup vs baseline: 2.7937x; 1.0834x over previous
#include <cuda_runtime.h>
#include <cstdint>

#define GRID_C 148

__device__ float G1d[2097152]; // [8192][256] = 1 - h1^2
__device__ float G2d[2097152]; // [8192][256] = 1 - h2^2
__device__ float W2P[65536];   // frag-permuted tf32 W2: [c][lt][ks][lane][2]
__device__ float W1P[16384];   // frag-permuted tf32 W1: [jt][ksg][lane][2]
__device__ float W3P[16384];   // frag-permuted tf32 W3^T (A-side): [mt][ks][lane][4]

typedef unsigned long long u64;
__device__ __forceinline__ float rnaf(float f){
    uint32_t o; asm("cvt.rna.tf32.f32 %0, %1;" : "=r"(o) : "f"(f)); return __uint_as_float(o);
}
__device__ __forceinline__ u64 pk2(float s){ u64 r; asm("mov.b64 %0,{%1,%1};" : "=l"(r) : "f"(s)); return r; }
__device__ __forceinline__ u64 fma2(u64 a, u64 b, u64 c){ u64 d; asm("fma.rn.f32x2 %0,%1,%2,%3;" : "=l"(d) : "l"(a), "l"(b), "l"(c)); return d; }
__device__ __forceinline__ void mma8(float* c, const uint32_t* a, const uint32_t* b){
    asm volatile("mma.sync.aligned.m16n8k8.row.col.f32.tf32.tf32.f32 "
        "{%0,%1,%2,%3},{%4,%5,%6,%7},{%8,%9},{%0,%1,%2,%3};"
        : "+f"(c[0]), "+f"(c[1]), "+f"(c[2]), "+f"(c[3])
        : "r"(a[0]), "r"(a[1]), "r"(a[2]), "r"(a[3]), "r"(b[0]), "r"(b[1]));
}
#define CPA(dst, src) asm volatile("cp.async.cg.shared.global [%0],[%1],16;" :: "r"(dst), "l"(src) : "memory")
__device__ __forceinline__ uint32_t su32(const void* p){
    uint32_t a; asm("{.reg .u64 t; cvta.to.shared.u64 t,%1; cvt.u32.u64 %0,t;}" : "=r"(a) : "l"(p)); return a;
}
#define WGBAR(id) asm volatile("bar.sync %0, 256;" :: "r"(id) : "memory")

// ---------------- prep: fragment-permuted tf32 weight images ----------------
__global__ void prep(const float* __restrict__ W1, const float* __restrict__ W2,
                     const float* __restrict__ W3){
    int i = blockIdx.x * blockDim.x + threadIdx.x, stride = gridDim.x * blockDim.x;
    for (int idx = i; idx < 65536; idx += stride){
        int w = idx & 1, lane = (idx >> 1) & 31, ks = (idx >> 6) & 31, lt = (idx >> 11) & 3, c = idx >> 13;
        int l = c * 32 + lt * 8 + (lane >> 2), k = ks * 8 + (lane & 3) + 4 * w;
        W2P[idx] = rnaf(W2[l * 256 + k]);
    }
    for (int idx = i; idx < 16384; idx += stride){
        int w = idx & 1, lane = (idx >> 1) & 31, ksg = (idx >> 6) & 31, jt = idx >> 11;
        int j = jt * 8 + (lane >> 2), l = ksg * 8 + (lane & 3) + 4 * w;
        W1P[idx] = rnaf(W1[j * 256 + l]);
    }
    for (int idx = i; idx < 16384; idx += stride){
        int w = idx & 3, lane = (idx >> 2) & 31, ks = (idx >> 7) & 31, mt = idx >> 12;
        int m = mt * 16 + (lane >> 2) + 8 * (w & 1);
        int k = ks * 8 + (lane & 3) + 4 * (w >> 1);
        W3P[idx] = rnaf(W3[k * 64 + m]);
    }
}

// ---------------- fwd: exact fp32 g1/g2 for all batches ----------------
__global__ void __launch_bounds__(256, 1) fwd(const float* __restrict__ x, const float* __restrict__ W1,
                                              const float* __restrict__ b1, const float* __restrict__ W2,
                                              const float* __restrict__ b2){
    extern __shared__ float fs[];
    float* xs  = fs;             // [64 j][66]
    float* h1t = fs + 64 * 66;   // [256 l][66]
    const int t = threadIdx.x;
    const int b0 = blockIdx.x * 64;
    for (int r = 0; r < 16; r++){
        int idx = r * 256 + t, b = idx >> 6, j = idx & 63;
        xs[j * 66 + b] = x[(size_t)(b0 + b) * 64 + j];
    }
    __syncthreads();
    u64 acc[32];
    #pragma unroll
    for (int q = 0; q < 32; q++) acc[q] = 0ull;
    for (int j = 0; j < 64; j++){
        u64 wp = pk2(W1[j * 256 + t]);
        const u64* xr = (const u64*)(xs + j * 66);
        #pragma unroll
        for (int q = 0; q < 32; q++) acc[q] = fma2(xr[q], wp, acc[q]);
    }
    float bb = b1[t];
    #pragma unroll
    for (int q = 0; q < 32; q++){
        float2 f; asm("mov.b64 {%0,%1},%2;" : "=f"(f.x), "=f"(f.y) : "l"(acc[q]));
        float ha = tanhf(f.x + bb), hb = tanhf(f.y + bb);
        h1t[t * 66 + 2*q] = ha; h1t[t * 66 + 2*q + 1] = hb;
        G1d[(size_t)(b0 + 2*q) * 256 + t]     = 1.f - ha * ha;
        G1d[(size_t)(b0 + 2*q + 1) * 256 + t] = 1.f - hb * hb;
    }
    __syncthreads();
    #pragma unroll
    for (int q = 0; q < 32; q++) acc[q] = 0ull;
    for (int l = 0; l < 256; l++){
        u64 wp = pk2(W2[l * 256 + t]);
        const u64* hr = (const u64*)(h1t + l * 66);
        #pragma unroll
        for (int q = 0; q < 32; q++) acc[q] = fma2(hr[q], wp, acc[q]);
    }
    bb = b2[t];
    #pragma unroll
    for (int q = 0; q < 32; q++){
        float2 f; asm("mov.b64 {%0,%1},%2;" : "=f"(f.x), "=f"(f.y) : "l"(acc[q]));
        float ha = tanhf(f.x + bb), hb = tanhf(f.y + bb);
        G2d[(size_t)(b0 + 2*q) * 256 + t]     = 1.f - ha * ha;
        G2d[(size_t)(b0 + 2*q + 1) * 256 + t] = 1.f - hb * hb;
    }
}

// ---------------- jmain: 512 thr, 2 batches/CTA, 4-chain m64 tiling ----------------
// smem floats: W3s 16384 | W2 ring 2x16384 | C1P 2x4096 | g2s 2x256
#define SMF (16384 + 32768 + 8192 + 512)

__global__ void __launch_bounds__(512, 1) jmain(float* __restrict__ out){
    extern __shared__ float s[];
    float* W3s = s;                 // 16384
    float* W2s = s + 16384;         // 2 x 16384 (chunk-pair ring)
    float* C1P = W2s + 32768;       // 2 x 4096
    float* g2s = C1P + 8192;        // 2 x 256

    const int t = threadIdx.x, lane = t & 31, wid = t >> 5;
    const int wg = wid >> 3, w8 = wid & 7;
    const int g = lane >> 2, tg = lane & 3;
    const int t2 = t & 255;

    float* C1w = C1P + wg * 4096;
    float* g2w = g2s + wg * 256;
    const uint32_t w3sb = su32(W3s);
    const uint32_t w2sb = su32(W2s);

    // resident W3P (A operand), loaded once
    #pragma unroll
    for (int i = 0; i < 8; i++){
        int u = t + i * 512;
        CPA(w3sb + (uint32_t)u * 16, (const char*)W3P + u * 16);
    }
    asm volatile("cp.async.commit_group;" ::: "memory");

    const float4* W3s4 = (const float4*)W3s + lane;
    const float4* C1w4 = (const float4*)C1w + lane;
    const float2* W1P2 = (const float2*)W1P + lane;

    for (int p = blockIdx.x; p < 4096; p += GRID_C){
        const int b = 2 * p + wg;
        g2w[t2] = G2d[(size_t)b * 256 + t2];
        // prefetch chunk-pair 0 into buf 0
        #pragma unroll
        for (int i = 0; i < 8; i++){
            int u = t + i * 512;
            CPA(w2sb + (uint32_t)u * 16, (const char*)W2P + u * 16);
        }
        asm volatile("cp.async.commit_group;" ::: "memory");

        float J[4][4];
        #pragma unroll
        for (int a = 0; a < 4; a++)
            #pragma unroll
            for (int q = 0; q < 4; q++) J[a][q] = 0.f;

        #pragma unroll 1
        for (int cp = 0; cp < 4; cp++){
            const int buf = cp & 1;
            asm volatile("cp.async.wait_group 0;" ::: "memory");
            __syncthreads();   // current buf published; all warps past previous cp
            if (cp < 3){
                const char* src = (const char*)W2P + (size_t)(cp + 1) * 65536;
                uint32_t dst = w2sb + (uint32_t)(buf ^ 1) * 65536;
                #pragma unroll
                for (int i = 0; i < 8; i++){
                    int u = t + i * 512;
                    CPA(dst + (uint32_t)u * 16, src + u * 16);
                }
                asm volatile("cp.async.commit_group;" ::: "memory");
            }

            // ---- GEMM1: C1r[4][4] = A(m64,k256) x B(n8,k256) with g2 folded into B ----
            float C1r[4][4];
            #pragma unroll
            for (int a = 0; a < 4; a++)
                #pragma unroll
                for (int q = 0; q < 4; q++) C1r[a][q] = 0.f;
            const float2* bp = (const float2*)(W2s + buf * 16384) + w8 * 1024 + lane;
            #pragma unroll 4
            for (int ks = 0; ks < 32; ks++){
                float ga = g2w[ks * 8 + tg], gb = g2w[ks * 8 + tg + 4];
                float2 Br = bp[ks * 32];
                float2 Bs; Bs.x = rnaf(Br.x * ga); Bs.y = rnaf(Br.y * gb);
                float4 A0 = W3s4[(0 * 32 + ks) * 32];
                float4 A1 = W3s4[(1 * 32 + ks) * 32];
                float4 A2 = W3s4[(2 * 32 + ks) * 32];
                float4 A3 = W3s4[(3 * 32 + ks) * 32];
                mma8(C1r[0], (const uint32_t*)&A0, (const uint32_t*)&Bs);
                mma8(C1r[1], (const uint32_t*)&A1, (const uint32_t*)&Bs);
                mma8(C1r[2], (const uint32_t*)&A2, (const uint32_t*)&Bs);
                mma8(C1r[3], (const uint32_t*)&A3, (const uint32_t*)&Bs);
            }

            // ---- park: scale by g1 (LDG, L1-hot), write frag-permuted A2 into C1P ----
            {
                const int gb0 = cp * 64 + w8 * 8;
                const float g1v0 = __ldg(&G1d[(size_t)b * 256 + gb0 + 2 * tg]);
                const float g1v1 = __ldg(&G1d[(size_t)b * 256 + gb0 + 2 * tg + 1]);
                const int l7a = 2 * tg, l7b = 2 * tg + 1;
                const int wa = 2 * (l7a >> 2), wb = 2 * (l7b >> 2);
                const int ca = (l7a & 3), cb = (l7b & 3);
                #pragma unroll
                for (int mt = 0; mt < 4; mt++){
                    const int base = ((mt * 8 + w8) * 32 + g * 4) * 4;
                    C1w[base + ca * 4 + wa]     = rnaf(C1r[mt][0] * g1v0);
                    C1w[base + cb * 4 + wb]     = rnaf(C1r[mt][1] * g1v1);
                    C1w[base + ca * 4 + wa + 1] = rnaf(C1r[mt][2] * g1v0);
                    C1w[base + cb * 4 + wb + 1] = rnaf(C1r[mt][3] * g1v1);
                }
            }
            WGBAR(1 + wg);

            // ---- GEMM2 partial: J += A2(m64,k64) x W1(n8,k64) ----
            {
                const float2* b2p = W1P2 + (w8 * 32 + cp * 8) * 32;
                #pragma unroll
                for (int ss = 0; ss < 8; ss++){
                    float4 A0 = C1w4[(0 * 8 + ss) * 32];
                    float4 A1 = C1w4[(1 * 8 + ss) * 32];
                    float4 A2 = C1w4[(2 * 8 + ss) * 32];
                    float4 A3 = C1w4[(3 * 8 + ss) * 32];
                    float2 B = b2p[ss * 32];
                    mma8(J[0], (const uint32_t*)&A0, (const uint32_t*)&B);
                    mma8(J[1], (const uint32_t*)&A1, (const uint32_t*)&B);
                    mma8(J[2], (const uint32_t*)&A2, (const uint32_t*)&B);
                    mma8(J[3], (const uint32_t*)&A3, (const uint32_t*)&B);
                }
            }
        }

        // ---- epilogue: J -> out[b] ----
        {
            float* ob = out + (size_t)b * 4096;
            const int cc = w8 * 8 + 2 * tg;
            #pragma unroll
            for (int mt = 0; mt < 4; mt++){
                const int r0 = mt * 16 + g;
                *(float2*)(ob + (size_t)r0 * 64 + cc)       = make_float2(J[mt][0], J[mt][1]);
                *(float2*)(ob + (size_t)(r0 + 8) * 64 + cc) = make_float2(J[mt][2], J[mt][3]);
            }
        }
    }
}

extern "C" void kernel_launch(void* const* d_in, const int* in_sizes, int n_in,
                              void* d_out, int out_size)
{
    const float* x  = (const float*)d_in[0];
    const float* W1 = (const float*)d_in[1];
    const float* b1 = (const float*)d_in[2];
    const float* W2 = (const float*)d_in[3];
    const float* b2 = (const float*)d_in[4];
    const float* W3 = (const float*)d_in[5];
    float* out = (float*)d_out;

    cudaFuncSetAttribute(fwd,   cudaFuncAttributeMaxDynamicSharedMemorySize, (64*66 + 256*66) * 4);
    cudaFuncSetAttribute(jmain, cudaFuncAttributeMaxDynamicSharedMemorySize, SMF * 4);

    prep<<<64, 256>>>(W1, W2, W3);
    fwd<<<128, 256, (64*66 + 256*66) * 4>>>(x, W1, b1, W2, b2);
    jmain<<<GRID_C, 512, SMF * 4>>>(out);
}